// round 16
// baseline (speedup 1.0000x reference)
#include <cuda_runtime.h>
#include <cstdint>

// fully_fix_linear, round 16: R15 structure + two chains per warp with a
// two-group cp.async pipeline (compute chain 0 overlaps chain 1's load).
//
// Math (exact on the 1/32 grid):
//   t_i = floor(32 * x[b,o,i] * w[o,i]);  c <- clamp(c + t_i, -127, 127), i=1023..0
//   out[b,o] = clamp(floor(32*(c/32 + bias[o])), -127, 127) / 32
// Warp-per-chain clamp-composition fold: lane k folds segment [32k,32k+32)
// into v -> min(max(v+A,L),H) (one-sided per-lane clamps: opposite bound
// needs a 254 swing in 32 elements, ~28 sigma); order-preserving shuffle
// tree with full clamps. Integers |.| < 2^24 -> exact f32. w prescaled by 32
// (RN(x*(32w)) == 32*RN(x*w): pow2 commutes with RN rounding).
//
// Block = 128 threads, one w row, 8 chains (2 per warp). Warp 0 is the w
// producer (bar.arrive, non-blocking); warps 1-3 wait only on their own x
// groups + bar.sync. Each warp: load x0 | load x1 | wait<=1> | compute x0
// (x1 still in flight) | wait<0> | compute x1.

constexpr int OUTD = 1024;
constexpr int VEC  = 256;                 // float4 per 4KB row

__device__ __forceinline__ int sw(int v) { return v ^ ((v >> 3) & 7); }
__device__ __forceinline__ unsigned su32(const void* p) {
    return (unsigned)__cvta_generic_to_shared(p);
}
__device__ __forceinline__ void cp16(void* sdst, const void* gsrc) {
    asm volatile("cp.async.cg.shared.global [%0], [%1], 16;\n"
                 :: "r"(su32(sdst)), "l"(gsrc));
}
__device__ __forceinline__ void cp16_ef(void* sdst, const void* gsrc,
                                        unsigned long long pol) {
    asm volatile("cp.async.cg.shared.global.L2::cache_hint [%0], [%1], 16, %2;\n"
                 :: "r"(su32(sdst)), "l"(gsrc), "l"(pol));
}
__device__ __forceinline__ void cp_commit() { asm volatile("cp.async.commit_group;"); }
template<int N> __device__ __forceinline__ void cp_wait() {
    asm volatile("cp.async.wait_group %0;" :: "n"(N));
}

__device__ __forceinline__ void step(float xe, float w32,
                                     float& A, float& L, float& H) {
    float t = floorf(__fmul_rn(xe, w32));   // == floor(32*RN(x*w))
    A = A + t;
    L = fmaxf(L + t, -127.0f);
    H = fminf(H + t,  127.0f);
}

__device__ __forceinline__ float chain(const float4* __restrict__ xb,
                                       const float4* __restrict__ wb, int lane) {
    float A = 0.0f, L = -127.0f, H = 127.0f;
    #pragma unroll
    for (int j = 7; j >= 0; --j) {          // descending i = application order
        int s = sw(lane * 8 + j);
        float4 xv = xb[s];
        float4 wv = wb[s];
        step(xv.w, wv.w, A, L, H);
        step(xv.z, wv.z, A, L, H);
        step(xv.y, wv.y, A, L, H);
        step(xv.x, wv.x, A, L, H);
    }
    #pragma unroll
    for (int s = 1; s < 32; s <<= 1) {      // lane k merges segment to its RIGHT
        float Ar = __shfl_down_sync(0xffffffffu, A, s);
        float Lr = __shfl_down_sync(0xffffffffu, L, s);
        float Hr = __shfl_down_sync(0xffffffffu, H, s);
        float Ln = fminf(fmaxf(Lr + A, L), H);
        float Hn = fminf(fmaxf(Hr + A, L), H);
        A = A + Ar;
        L = Ln;
        H = Hn;
    }
    return fminf(fmaxf(A, L), H);           // composed map applied to 0
}

__global__ void __launch_bounds__(128)
ffl_kernel(const float* __restrict__ x, const float* __restrict__ w,
           const float* __restrict__ bias, float* __restrict__ out)
{
    __shared__ float4 wsm[VEC];             // 32*w row (4KB)
    __shared__ float4 xs[4][2][VEC];        // per-warp two x rows (32KB)

    const int warp = threadIdx.x >> 5;
    const int lane = threadIdx.x & 31;
    const int o  = blockIdx.x >> 2;         // 0..1023 (4 blocks share o)
    const int bg = blockIdx.x & 3;
    const int b0 = bg * 8 + warp * 2;       // this warp's two batches
    const int b1 = b0 + 1;

    unsigned long long pol;                 // x streamed once -> evict_first
    asm("createpolicy.fractional.L2::evict_first.b64 %0, 1.0;" : "=l"(pol));

    auto ld_x = [&](int b, int slot) {
        const float4* xv = reinterpret_cast<const float4*>(x)
                         + ((size_t)b * OUTD + o) * VEC;
        #pragma unroll
        for (int j = 0; j < 8; ++j) {
            int v = j * 32 + lane;
            cp16_ef(&xs[warp][slot][sw(v)], xv + v, pol);
        }
        cp_commit();
    };

    if (warp == 0) {
        ld_x(b0, 0);                        // group: x0
        {                                   // group: w (needed before compute)
            const float4* wv = reinterpret_cast<const float4*>(w) + (size_t)o * VEC;
            #pragma unroll
            for (int j = 0; j < 8; ++j) {
                int v = j * 32 + lane;
                cp16(&wsm[sw(v)], wv + v);  // default policy: L2-reused
            }
            cp_commit();
        }
        ld_x(b1, 1);                        // group: x1
    } else {
        ld_x(b0, 0);
        ld_x(b1, 1);
    }
    const float bo = __ldg(&bias[o]);       // overlaps the cp waits

    if (warp == 0) {
        cp_wait<1>();                       // x0 + w landed (x1 may be in flight)
        #pragma unroll
        for (int j = 0; j < 8; ++j) {
            int s = sw(j * 32 + lane);
            float4 a = wsm[s];
            a.x *= 32.0f; a.y *= 32.0f; a.z *= 32.0f; a.w *= 32.0f;
            wsm[s] = a;
        }
        __syncwarp();
        asm volatile("bar.arrive 1, 128;" ::: "memory");   // non-blocking
    } else {
        cp_wait<1>();                       // own x0 landed
        asm volatile("bar.sync 1, 128;" ::: "memory");     // w ready
    }

    // Chain 0 (x1's load still in flight underneath).
    {
        float c = chain(xs[warp][0], wsm, lane);
        if (lane == 0) {
            float v = c * 0.03125f + bo;
            float r = floorf(v * 32.0f);
            r = fminf(fmaxf(r, -127.0f), 127.0f);
            out[(size_t)b0 * OUTD + o] = r * 0.03125f;
        }
    }
    // Chain 1.
    cp_wait<0>();
    __syncwarp();
    {
        float c = chain(xs[warp][1], wsm, lane);
        if (lane == 0) {
            float v = c * 0.03125f + bo;
            float r = floorf(v * 32.0f);
            r = fminf(fmaxf(r, -127.0f), 127.0f);
            out[(size_t)b1 * OUTD + o] = r * 0.03125f;
        }
    }
}

extern "C" void kernel_launch(void* const* d_in, const int* in_sizes, int n_in,
                              void* d_out, int out_size)
{
    const float* x    = (const float*)d_in[0];
    const float* w    = (const float*)d_in[1];
    const float* bias = (const float*)d_in[2];
    float* out        = (float*)d_out;

    // 32768 chains, 8 per block (2 per warp): 4096 blocks x 128 threads.
    ffl_kernel<<<4096, 128>>>(x, w, bias, out);
}